// round 17
// baseline (speedup 1.0000x reference)
#include <cuda_runtime.h>
#include <cstdint>

// KA_BSpline_Core: out[n] = b_out + sum_q a[q] * spline_q( sigmoid(2*scale*(emb[n]·W[q]+b_inner[q])) )
//
// R17 = R5 mainloop (best: 104.4us) + polynomial-table epilogue.
// On each knot span the spline contribution a[q]*phi_q(s) is a fixed cubic.
// A tiny FP64 precompute kernel builds poly[q][span] = (c0..c3) once per
// launch; the epilogue becomes sigmoid + 1 LDS.128 + 3-FMA Horner per q
// (was ~55 instr incl. 6 MUFU.RCP de Boor divisions). ~17% fewer
// instructions total, 70% fewer MUFU ops. Mainloop byte-identical to R5.

#define QDIM   12
#define KDIM   256
#define NCTRL  25
#define NSPAN  22
#define BLOCK  128
#define TILE   256           // points per block (2 per thread)
#define KCH    16
#define NCHUNK (KDIM / KCH)  // 16
#define BUF_FLOATS (TILE * KCH)                  // 4096
#define POLY_FLOATS (QDIM * NSPAN * 4)           // 1056
#define SMEM_FLOATS (2*BUF_FLOATS + POLY_FLOATS + QDIM*KDIM + 16)
#define SMEM_BYTES  (SMEM_FLOATS * 4)

__device__ float4 g_poly[QDIM * NSPAN];

__device__ __forceinline__ unsigned long long fma2(unsigned long long a,
                                                   unsigned long long b,
                                                   unsigned long long c) {
    unsigned long long d;
    asm("fma.rn.f32x2 %0, %1, %2, %3;" : "=l"(d) : "l"(a), "l"(b), "l"(c));
    return d;
}

// ---- precompute: per (q, span) cubic a[q]*phi_q as monomial coeffs in t=22s-j ----
__global__ void precompute_poly(const float* __restrict__ coeffs,
                                const float* __restrict__ a_out) {
    int idx = threadIdx.x;
    if (idx >= QDIM * NSPAN) return;
    int q = idx / NSPAN, j = idx % NSPAN;

    auto knot = [](int t) -> double {
        t -= 3; t = t < 0 ? 0 : (t > 22 ? 22 : t);
        return (double)t / 22.0;
    };

    double f[4];
#pragma unroll
    for (int m = 0; m < 4; m++) {
        double t = (double)m / 3.0;
        double s = ((double)j + t) / 22.0;
        const int i = j + 3;
        double Nb[4], lft[4], rgt[4];
        Nb[0] = 1.0;
        for (int p = 1; p <= 3; p++) {
            lft[p] = s - knot(i + 1 - p);
            rgt[p] = knot(i + p) - s;
            double saved = 0.0;
            for (int r = 0; r < p; r++) {
                double den = rgt[r + 1] + lft[p - r];
                double tmp = Nb[r] / den;
                Nb[r] = rgt[r + 1] * tmp + saved;
                saved = lft[p - r] * tmp;
            }
            Nb[p] = saved;
        }
        double phi = 0.0;
        for (int r = 0; r < 4; r++)
            phi += Nb[r] * (double)coeffs[q * NCTRL + j + r];
        f[m] = phi * (double)a_out[q];
    }
    // exact cubic through nodes t = 0, 1/3, 2/3, 1 (inverse Vandermonde)
    double c0 = f[0];
    double c1 = (-11.0*f[0] + 18.0*f[1] -  9.0*f[2] + 2.0*f[3]) * 0.5;
    double c2 = ( 18.0*f[0] - 45.0*f[1] + 36.0*f[2] - 9.0*f[3]) * 0.5;
    double c3 = ( -9.0*f[0] + 27.0*f[1] - 27.0*f[2] + 9.0*f[3]) * 0.5;
    g_poly[idx] = make_float4((float)c0, (float)c1, (float)c2, (float)c3);
}

__global__ __launch_bounds__(BLOCK, 4)
void kan_bspline_kernel(const float* __restrict__ emb,
                        const float* __restrict__ W,
                        const float* __restrict__ b_inner,
                        const float* __restrict__ inner_scale,
                        const float* __restrict__ b_out,
                        float* __restrict__ out,
                        int npts) {
    extern __shared__ float sh[];
    float*  bufs = sh;                           // 2 * BUF_FLOATS
    float4* Psh  = (float4*)(sh + 2 * BUF_FLOATS);   // QDIM*NSPAN float4
    float*  Wsh  = sh + 2 * BUF_FLOATS + POLY_FLOATS; // QDIM*KDIM = 3072
    float*  Msh  = Wsh + QDIM * KDIM;            // [0..11]=b_inner [12]=scale [13]=b_out

    const int tid  = threadIdx.x;
    const int wid  = tid >> 5;                 // warp 0..3
    const int lane = tid & 31;
    const long long tile0 = (long long)blockIdx.x * TILE;
    const bool full_tile = (tile0 + TILE) <= (long long)npts;

    // ---- warp-private cp.async loader (identical to R5) ----
    // Warp w loads exactly the 64 rows its own lanes consume:
    //   rows w*32..w*32+31 (acc0) and +128 (acc1).
    // Lane l covers float4-slot (l&3) of rows (w*32 + (l>>2) + 8i), i=0..3.
    // XOR swizzle: slot = ccol ^ ((row>>1)&3) -> conflict-free fill & read.
    const int ccol  = lane & 3;
    const int rsub  = lane >> 2;               // 0..7
    const int rbase = wid * 32 + rsub;

    auto issue = [&](int kc, int b) {
        float* bb = bufs + b * BUF_FLOATS;
        const float* g0 = emb + kc * KCH + ccol * 4;
        if (full_tile) {
#pragma unroll
            for (int h = 0; h < 2; h++) {
#pragma unroll
                for (int i = 0; i < 4; i++) {
                    int row = h * 128 + rbase + 8 * i;
                    int slot = ccol ^ ((row >> 1) & 3);
                    unsigned sa = (unsigned)__cvta_generic_to_shared(bb + row * KCH + slot * 4);
                    asm volatile("cp.async.cg.shared.global [%0], [%1], 16;\n"
                                 :: "r"(sa), "l"(g0 + (tile0 + row) * KDIM));
                }
            }
        } else {
#pragma unroll
            for (int h = 0; h < 2; h++) {
#pragma unroll
                for (int i = 0; i < 4; i++) {
                    int row = h * 128 + rbase + 8 * i;
                    long long prow = tile0 + row;
                    int ok = (prow < (long long)npts);
                    const float* gp = ok ? (g0 + prow * KDIM) : emb;
                    int sz = ok ? 16 : 0;
                    int slot = ccol ^ ((row >> 1) & 3);
                    unsigned sa = (unsigned)__cvta_generic_to_shared(bb + row * KCH + slot * 4);
                    asm volatile("cp.async.cg.shared.global [%0], [%1], 16, %2;\n"
                                 :: "r"(sa), "l"(gp), "r"(sz));
                }
            }
        }
        asm volatile("cp.async.commit_group;\n" ::: "memory");
    };

    issue(0, 0);

    // ---- stage constants into smem ----
    for (int i = tid; i < QDIM * KDIM / 4; i += BLOCK)
        ((float4*)Wsh)[i] = ((const float4*)W)[i];
    for (int i = tid; i < QDIM * NSPAN; i += BLOCK)
        Psh[i] = g_poly[i];
    if (tid < QDIM) Msh[tid] = b_inner[tid];
    if (tid == 0)   { Msh[12] = inner_scale[0]; Msh[13] = b_out[0]; }
    __syncthreads();   // the only block barrier

    unsigned long long acc0[QDIM], acc1[QDIM];
#pragma unroll
    for (int q = 0; q < QDIM; q++) { acc0[q] = 0ULL; acc1[q] = 0ULL; }

    const int sw = (tid >> 1) & 3;   // read-side swizzle (same for row tid and tid+128)

#pragma unroll 1
    for (int c = 0; c < NCHUNK; c++) {
        if (c + 1 < NCHUNK) {
            issue(c + 1, (c + 1) & 1);
            asm volatile("cp.async.wait_group 1;\n" ::: "memory");
        } else {
            asm volatile("cp.async.wait_group 0;\n" ::: "memory");
        }
        __syncwarp();

        const float* row0 = bufs + (c & 1) * BUF_FLOATS + tid * KCH;
        const float* row1 = row0 + BLOCK * KCH;         // point tid + 128
        const float* wb   = Wsh + c * KCH;
#pragma unroll
        for (int k4 = 0; k4 < KCH / 4; k4++) {
            const int slot = (k4 ^ sw) * 4;
            ulonglong2 x0 = *(const ulonglong2*)(row0 + slot);
            ulonglong2 x1 = *(const ulonglong2*)(row1 + slot);
#pragma unroll
            for (int q = 0; q < QDIM; q++) {
                ulonglong2 w = *(const ulonglong2*)(wb + q * KDIM + k4 * 4);
                acc0[q] = fma2(x0.x, w.x, acc0[q]);
                acc0[q] = fma2(x0.y, w.y, acc0[q]);
                acc1[q] = fma2(x1.x, w.x, acc1[q]);
                acc1[q] = fma2(x1.y, w.y, acc1[q]);
            }
        }
        __syncwarp();
    }

    // ---- epilogue: sigmoid + per-span cubic Horner for both points ----
    const float is = Msh[12];
#pragma unroll
    for (int pp = 0; pp < 2; pp++) {
        long long myp = tile0 + tid + pp * BLOCK;
        if (myp >= (long long)npts) break;
        const unsigned long long* acc = pp ? acc1 : acc0;
        float res = Msh[13];
#pragma unroll
        for (int q = 0; q < QDIM; q++) {
            float lo, hi;
            asm("mov.b64 {%0, %1}, %2;" : "=f"(lo), "=f"(hi) : "l"(acc[q]));
            float u = lo + hi + Msh[q];
            // s = 0.5*(tanh(is*u)+1) = 1/(1+exp(-2*is*u))
            float e = __expf(-2.0f * is * u);
            float s = __fdividef(1.0f, 1.0f + e);

            float x22 = s * 22.0f;
            int j = (int)x22;
            j = j < 0 ? 0 : (j > 21 ? 21 : j);
            float t = x22 - (float)j;

            float4 P = Psh[q * NSPAN + j];
            // res += a[q]*phi = ((P.w*t + P.z)*t + P.y)*t + P.x
            float h2 = fmaf(P.w, t, P.z);
            float h1 = fmaf(h2, t, P.y);
            res += fmaf(h1, t, P.x);
        }
        out[myp] = res;
    }
}

extern "C" void kernel_launch(void* const* d_in, const int* in_sizes, int n_in,
                              void* d_out, int out_size) {
    const float* emb         = (const float*)d_in[0];
    const float* W           = (const float*)d_in[1];
    const float* b_inner     = (const float*)d_in[2];
    const float* inner_scale = (const float*)d_in[3];
    const float* coeffs      = (const float*)d_in[4];
    const float* a           = (const float*)d_in[5];
    const float* b_out       = (const float*)d_in[6];
    float* out = (float*)d_out;

    int npts = out_size;   // (N_POINTS, 1) float32
    int blocks = (npts + TILE - 1) / TILE;

    precompute_poly<<<1, QDIM * NSPAN>>>(coeffs, a);

    cudaFuncSetAttribute(kan_bspline_kernel,
                         cudaFuncAttributeMaxDynamicSharedMemorySize, SMEM_BYTES);
    kan_bspline_kernel<<<blocks, BLOCK, SMEM_BYTES>>>(
        emb, W, b_inner, inner_scale, b_out, out, npts);
}